// round 16
// baseline (speedup 1.0000x reference)
#include <cuda_runtime.h>
#include <cuda_fp16.h>
#include <math.h>
#include <stdint.h>

#define TOK  8192
#define DDIM 512
#define HDIM 2048
#define NEXP 4

// ---------------- device scratch ----------------
__device__ int   g_cnt[NEXP];
__device__ int   g_bucket[NEXP * TOK];
__device__ float g_sw[TOK];

__device__ __half g_xf[(size_t)TOK * DDIM];
__device__ __half g_he[(size_t)TOK * HDIM];           // expert-path hidden
__device__ __half g_hs[(size_t)TOK * HDIM];           // shared-path hidden
__device__ __half g_w1[(size_t)NEXP * DDIM * HDIM];   // [E][D][H]
__device__ __half g_w2[(size_t)NEXP * HDIM * DDIM];   // [E][H][D]
__device__ __half g_s1[(size_t)DDIM * HDIM];          // [D][H]
__device__ __half g_s2[(size_t)HDIM * DDIM];          // [H][D]

// ---------------- helpers ----------------
__device__ __forceinline__ uint32_t smem_u32(const void* p) {
    uint32_t a;
    asm("{ .reg .u64 t; cvta.to.shared.u64 t, %1; cvt.u32.u64 %0, t; }" : "=r"(a) : "l"(p));
    return a;
}
__device__ __forceinline__ void cp16(uint32_t dst, const void* src, bool valid) {
    int sz = valid ? 16 : 0;
    asm volatile("cp.async.cg.shared.global [%0], [%1], 16, %2;\n" :: "r"(dst), "l"(src), "r"(sz));
}
#define CP_COMMIT() asm volatile("cp.async.commit_group;\n" ::: "memory")
#define CP_WAIT2()  asm volatile("cp.async.wait_group 2;\n" ::: "memory")

__device__ __forceinline__ void ldsm4(uint32_t& r0, uint32_t& r1, uint32_t& r2, uint32_t& r3,
                                      uint32_t a) {
    asm volatile("ldmatrix.sync.aligned.m8n8.x4.shared.b16 {%0,%1,%2,%3}, [%4];"
        : "=r"(r0), "=r"(r1), "=r"(r2), "=r"(r3) : "r"(a));
}
__device__ __forceinline__ void ldsm4t(uint32_t& r0, uint32_t& r1, uint32_t& r2, uint32_t& r3,
                                       uint32_t a) {
    asm volatile("ldmatrix.sync.aligned.m8n8.x4.trans.shared.b16 {%0,%1,%2,%3}, [%4];"
        : "=r"(r0), "=r"(r1), "=r"(r2), "=r"(r3) : "r"(a));
}
__device__ __forceinline__ void mma16816(float* c, const uint32_t* a, const uint32_t* b) {
    asm volatile("mma.sync.aligned.m16n8k16.row.col.f32.f16.f16.f32 "
        "{%0,%1,%2,%3}, {%4,%5,%6,%7}, {%8,%9}, {%0,%1,%2,%3};"
        : "+f"(c[0]), "+f"(c[1]), "+f"(c[2]), "+f"(c[3])
        : "r"(a[0]), "r"(a[1]), "r"(a[2]), "r"(a[3]), "r"(b[0]), "r"(b[1]));
}

// vectorized global reduction add of a float2 (8B-aligned dst), sm_90+
__device__ __forceinline__ void red_add_v2(float* dst, float a, float b) {
    asm volatile("red.global.add.v2.f32 [%0], {%1, %2};"
        :: "l"(dst), "f"(a), "f"(b) : "memory");
}

// fast gelu: x * sigmoid(1.5957692*(x + 0.044715 x^3))  (tanh-form rewrite)
__device__ __forceinline__ float fast_gelu(float x) {
    float u = x * fmaf(0.07135481627f, x * x, 1.5957691216f);
    return __fdividef(x, 1.f + __expf(-u));
}

// ---------------- zero counters ----------------
__global__ void zero_kernel() {
    if (threadIdx.x < NEXP) g_cnt[threadIdx.x] = 0;
}

// ---------------- router: smem gW + 2 tokens/warp, batched x loads, fused x->fp16 ----------------
#define RT_TPW 2
__global__ __launch_bounds__(256)
void router_kernel(const float* __restrict__ x,
                   const float* __restrict__ gW,
                   const float* __restrict__ gb,
                   const float* __restrict__ shw,
                   float* __restrict__ gate_out,
                   __half* __restrict__ xf) {
    __shared__ float sgWt[NEXP][DDIM];   // gW transposed: [expert][d]
    const int tid = threadIdx.x;

    // cooperative load + transpose of gW (8 KB)
    #pragma unroll
    for (int r = 0; r < 2; r++) {
        int d = tid + 256 * r;
        float4 w = *(const float4*)(gW + 4 * d);
        sgWt[0][d] = w.x; sgWt[1][d] = w.y; sgWt[2][d] = w.z; sgWt[3][d] = w.w;
    }

    const int wid = tid >> 5, lane = tid & 31;
    const int tbase = (blockIdx.x * 8 + wid) * RT_TPW;

    // ---- front-batched x loads: 2 tokens x 4 float4 chunks, MLP = 8 ----
    float4 xv[RT_TPW][4];
    #pragma unroll
    for (int k = 0; k < RT_TPW; k++) {
        const float4* xr = (const float4*)(x + (size_t)(tbase + k) * DDIM);
        #pragma unroll
        for (int it = 0; it < 4; it++)
            xv[k][it] = xr[lane + 32 * it];
    }
    __syncthreads();    // gW transpose visible

    float a[RT_TPW][4];
    #pragma unroll
    for (int k = 0; k < RT_TPW; k++)
        #pragma unroll
        for (int e = 0; e < 4; e++) a[k][e] = 0.f;

    #pragma unroll
    for (int it = 0; it < 4; it++) {
        int j4 = lane + 32 * it;           // float4 index within a row
        float4 w[4];
        #pragma unroll
        for (int e = 0; e < 4; e++)
            w[e] = *(const float4*)(&sgWt[e][4 * j4]);   // conflict-free LDS.128
        #pragma unroll
        for (int k = 0; k < RT_TPW; k++) {
            float4 v = xv[k][it];
            #pragma unroll
            for (int e = 0; e < 4; e++)
                a[k][e] = fmaf(v.x, w[e].x, fmaf(v.y, w[e].y,
                           fmaf(v.z, w[e].z, fmaf(v.w, w[e].w, a[k][e]))));
        }
    }

    // xf stores from registers
    #pragma unroll
    for (int k = 0; k < RT_TPW; k++) {
        __half2* xo = (__half2*)(xf + (size_t)(tbase + k) * DDIM);
        #pragma unroll
        for (int it = 0; it < 4; it++) {
            int j4 = lane + 32 * it;
            float4 v = xv[k][it];
            xo[2 * j4]     = __halves2half2(__float2half(v.x), __float2half(v.y));
            xo[2 * j4 + 1] = __halves2half2(__float2half(v.z), __float2half(v.w));
        }
    }

    // butterfly-reduce accumulators across the warp
    #pragma unroll
    for (int off = 16; off > 0; off >>= 1)
        #pragma unroll
        for (int k = 0; k < RT_TPW; k++)
            #pragma unroll
            for (int e = 0; e < 4; e++)
                a[k][e] += __shfl_xor_sync(0xffffffffu, a[k][e], off);

    if (lane < RT_TPW) {
        int t = tbase + lane;
        float l[4];
        #pragma unroll
        for (int e = 0; e < 4; e++) l[e] = a[lane][e] + gb[e];
        float m = fmaxf(fmaxf(l[0], l[1]), fmaxf(l[2], l[3]));
        float ex[4], s = 0.f;
        #pragma unroll
        for (int e = 0; e < 4; e++) { ex[e] = expf(l[e] - m); s += ex[e]; }
        float inv = 1.f / s;
        float best = -1.f; int bi = 0;
        #pragma unroll
        for (int e = 0; e < 4; e++) {
            float g = ex[e] * inv;
            gate_out[4 * t + e] = g;
            if (g > best) { best = g; bi = e; }
        }
        float sig = 1.f / (1.f + expf(-shw[0]));
        g_sw[t] = (1.f - best) * sig;
        int pos = atomicAdd(&g_cnt[bi], 1);
        g_bucket[bi * TOK + pos] = t;
    }
}

// ---------------- aux loss ----------------
__global__ void aux_kernel(const float* __restrict__ gate, float* __restrict__ auxp) {
    __shared__ float4 s[1024];
    int tid = threadIdx.x;
    float4 a = make_float4(0.f, 0.f, 0.f, 0.f);
    for (int t = tid; t < TOK; t += 1024) {
        a.x += gate[4 * t + 0]; a.y += gate[4 * t + 1];
        a.z += gate[4 * t + 2]; a.w += gate[4 * t + 3];
    }
    s[tid] = a;
    __syncthreads();
    for (int off = 512; off > 0; off >>= 1) {
        if (tid < off) {
            s[tid].x += s[tid + off].x; s[tid].y += s[tid + off].y;
            s[tid].z += s[tid + off].z; s[tid].w += s[tid + off].w;
        }
        __syncthreads();
    }
    if (tid == 0) {
        const float invT = 1.f / (float)TOK;
        float gm[4] = { s[0].x * invT, s[0].y * invT, s[0].z * invT, s[0].w * invT };
        float aux = 0.f;
        #pragma unroll
        for (int e = 0; e < NEXP; e++) aux += ((float)g_cnt[e] * invT) * gm[e];
        *auxp = aux * (float)NEXP * 0.01f;
    }
}

// ---------------- split fp32 -> fp16 converts ----------------
#define N4_W  (NEXP * DDIM * HDIM / 4)
#define N4_S  (DDIM * HDIM / 4)
#define N4_C1 (N4_W + N4_S)             // W1 + sW1
#define N4_C2 (N4_W + N4_S)             // W2 + sW2

__global__ void convert1_kernel(const float* __restrict__ W1,
                                const float* __restrict__ sW1,
                                __half* w1, __half* s1) {
    int i = blockIdx.x * blockDim.x + threadIdx.x;
    if (i >= N4_C1) return;
    const float* src; __half* dst; int j = i;
    if (j < N4_W) { src = W1; dst = w1; }
    else { j -= N4_W; src = sW1; dst = s1; }
    float4 v = ((const float4*)src)[j];
    ((__half2*)dst)[2 * j]     = __halves2half2(__float2half(v.x), __float2half(v.y));
    ((__half2*)dst)[2 * j + 1] = __halves2half2(__float2half(v.z), __float2half(v.w));
}

__global__ void convert2_kernel(const float* __restrict__ W2,
                                const float* __restrict__ sW2,
                                __half* w2, __half* s2) {
    int i = blockIdx.x * blockDim.x + threadIdx.x;
    if (i >= N4_C2) return;
    const float* src; __half* dst; int j = i;
    if (j < N4_W) { src = W2; dst = w2; }
    else { j -= N4_W; src = sW2; dst = s2; }
    float4 v = ((const float4*)src)[j];
    ((__half2*)dst)[2 * j]     = __halves2half2(__float2half(v.x), __float2half(v.y));
    ((__half2*)dst)[2 * j + 1] = __halves2half2(__float2half(v.z), __float2half(v.w));
}

// ---------------- fp16 mma.sync GEMM, CTA 128x128, warp tile 64x32, 4-stage ----------------
// Independent expert (SP=false, z=expert) and shared (SP=true) chains.
// STAGE 1: A=xf, B=W1/sW1 -> fast_gelu -> he/hs
// STAGE 2: A=he/hs, B=W2/sW2 -> red.v2 into zeroed out (shared scaled by g_sw)
#define A_TILE_B 10240               // 128 rows * 80B
#define B_TILE_B 8704                // 32 rows * 272B
#define B_OFF    A_TILE_B
#define STAGE_B  (A_TILE_B + B_TILE_B)   // 18944
#define NSTAGE   4
#define SMEM_GEMM (NSTAGE * STAGE_B)     // 75776

template<int STAGE, bool SP>
__global__ __launch_bounds__(256, 2)
void mma_gemm(const __half* __restrict__ A_g,
              const __half* __restrict__ B_g,
              const float* __restrict__ bias_g,
              __half* __restrict__ hdst_g,
              float* __restrict__ outp,
              int K, int N)
{
    extern __shared__ __align__(16) char smem[];
    const int z = blockIdx.z;
    int Mtot = TOK;
    const int* bucket = nullptr;
    const __half* Bg = SP ? B_g : B_g + (size_t)z * (size_t)K * N;
    const float* bias = SP ? bias_g : bias_g + (size_t)z * N;
    if (!SP) {
        Mtot = g_cnt[z];
        if ((int)(blockIdx.y * 128) >= Mtot) return;
        bucket = g_bucket + z * TOK;
    }
    const int tid = threadIdx.x;
    const int wid = tid >> 5, lane = tid & 31;
    const int mbase = blockIdx.y * 128, nbase = blockIdx.x * 128;
    const uint32_t sb = smem_u32(smem);

    // ---- A loader ----
    const int rA0 = tid >> 2, rA1 = 64 + (tid >> 2);
    const int ck  = tid & 3;
    int tok0, tok1; bool v0, v1;
    if (!SP) {
        v0 = (mbase + rA0) < Mtot; tok0 = v0 ? bucket[mbase + rA0] : 0;
        v1 = (mbase + rA1) < Mtot; tok1 = v1 ? bucket[mbase + rA1] : 0;
    } else {
        v0 = v1 = true; tok0 = mbase + rA0; tok1 = mbase + rA1;
    }
    const __half* aP0 = A_g + (size_t)tok0 * K + ck * 8;
    const __half* aP1 = A_g + (size_t)tok1 * K + ck * 8;
    const uint32_t oA0 = (uint32_t)rA0 * 80 + ck * 16;
    const uint32_t oA1 = (uint32_t)rA1 * 80 + ck * 16;

    // ---- B loader ----
    const int rB = tid >> 3, cB = tid & 7;
    const __half* bp = Bg + (size_t)rB * N + nbase + cB * 8;
    const uint32_t oB = (uint32_t)rB * 272 + cB * 16;

    #define LOAD_STAGE(stg, koff) do {                                       \
        uint32_t b_ = sb + (uint32_t)(stg) * STAGE_B;                        \
        cp16(b_ + oA0, aP0 + (koff), v0);                                    \
        cp16(b_ + oA1, aP1 + (koff), v1);                                    \
        cp16(b_ + B_OFF + oB,       bp + (size_t)(koff) * N, true);          \
        cp16(b_ + B_OFF + oB + 128, bp + (size_t)(koff) * N + 64, true);     \
    } while (0)

    const int KT = K / 32;
    LOAD_STAGE(0, 0);  CP_COMMIT();
    LOAD_STAGE(1, 32); CP_COMMIT();
    LOAD_STAGE(2, 64); CP_COMMIT();

    // ---- compute mapping: warp tile 64 (M) x 32 (N) ----
    const int warpM = (wid & 1) * 64;
    const int warpN = (wid >> 1) * 32;
    float acc[4][4][4];
    #pragma unroll
    for (int mi = 0; mi < 4; mi++)
        #pragma unroll
        for (int ni = 0; ni < 4; ni++)
            #pragma unroll
            for (int q = 0; q < 4; q++) acc[mi][ni][q] = 0.f;

    const uint32_t aRowOff = (uint32_t)(warpM + (lane & 15)) * 80 + (lane >> 4) * 16;
    const uint32_t bOffBase = (uint32_t)((lane & 7) + ((lane >> 3) & 1) * 8) * 272
                              + (uint32_t)warpN * 2 + (uint32_t)(lane >> 4) * 16;

    int s_c = 0;
    for (int kt = 0; kt < KT; kt++) {
        CP_WAIT2();
        __syncthreads();
        if (kt + 3 < KT) {
            int s_l = s_c + 3; if (s_l >= NSTAGE) s_l -= NSTAGE;
            LOAD_STAGE(s_l, (kt + 3) * 32);
        }
        CP_COMMIT();

        uint32_t base = sb + (uint32_t)s_c * STAGE_B;
        #pragma unroll
        for (int ks = 0; ks < 2; ks++) {
            uint32_t bF[4][2];
            #pragma unroll
            for (int p = 0; p < 2; p++) {
                uint32_t r0, r1, r2, r3;
                ldsm4t(r0, r1, r2, r3,
                       base + B_OFF + bOffBase + (uint32_t)ks * (16 * 272) + (uint32_t)p * 32);
                bF[2 * p][0] = r0; bF[2 * p][1] = r1;
                bF[2 * p + 1][0] = r2; bF[2 * p + 1][1] = r3;
            }
            uint32_t aF[4][4];
            #pragma unroll
            for (int mi = 0; mi < 4; mi++) {
                uint32_t ad = base + aRowOff + (uint32_t)mi * (16 * 80) + ks * 32;
                ldsm4(aF[mi][0], aF[mi][1], aF[mi][2], aF[mi][3], ad);
            }
            #pragma unroll
            for (int mi = 0; mi < 4; mi++)
                #pragma unroll
                for (int ni = 0; ni < 4; ni++)
                    mma16816(acc[mi][ni], aF[mi], bF[ni]);
        }
        s_c = (s_c + 1 == NSTAGE) ? 0 : s_c + 1;
    }

    // ---- epilogue ----
    float bb[4][2];
    #pragma unroll
    for (int ni = 0; ni < 4; ni++) {
        int n = nbase + warpN + ni * 8 + (lane & 3) * 2;
        bb[ni][0] = bias[n]; bb[ni][1] = bias[n + 1];
    }

    #pragma unroll
    for (int mi = 0; mi < 4; mi++) {
        #pragma unroll
        for (int h = 0; h < 2; h++) {
            int pos = mbase + warpM + mi * 16 + (lane >> 2) + h * 8;
            int et; bool ev;
            if (!SP) { ev = pos < Mtot; et = ev ? bucket[pos] : 0; }
            else { ev = true; et = pos; }
            if (!ev) continue;
            float swv = (STAGE == 2 && SP) ? g_sw[et] : 1.f;
            #pragma unroll
            for (int ni = 0; ni < 4; ni++) {
                int n = nbase + warpN + ni * 8 + (lane & 3) * 2;
                float u0 = acc[mi][ni][2 * h]     + bb[ni][0];
                float u1 = acc[mi][ni][2 * h + 1] + bb[ni][1];
                if (STAGE == 1) {
                    u0 = fast_gelu(u0);
                    u1 = fast_gelu(u1);
                    *(__half2*)(hdst_g + (size_t)et * HDIM + n) =
                        __halves2half2(__float2half(u0), __float2half(u1));
                } else {
                    red_add_v2(outp + (size_t)et * DDIM + n, swv * u0, swv * u1);
                }
            }
        }
    }
    #undef LOAD_STAGE
}

// ---------------- launch ----------------
extern "C" void kernel_launch(void* const* d_in, const int* in_sizes, int n_in,
                              void* d_out, int out_size) {
    const float* x   = (const float*)d_in[0];
    const float* gW  = (const float*)d_in[1];
    const float* gb  = (const float*)d_in[2];
    const float* W1  = (const float*)d_in[3];
    const float* b1  = (const float*)d_in[4];
    const float* W2  = (const float*)d_in[5];
    const float* b2  = (const float*)d_in[6];
    const float* sW1 = (const float*)d_in[7];
    const float* sb1 = (const float*)d_in[8];
    const float* sW2 = (const float*)d_in[9];
    const float* sb2 = (const float*)d_in[10];
    const float* shw = (const float*)d_in[11];

    float* out  = (float*)d_out;
    float* auxp = out + (size_t)TOK * DDIM;
    float* gate = auxp + 1;

    cudaFuncSetAttribute(mma_gemm<1, false>, cudaFuncAttributeMaxDynamicSharedMemorySize, SMEM_GEMM);
    cudaFuncSetAttribute(mma_gemm<1, true>,  cudaFuncAttributeMaxDynamicSharedMemorySize, SMEM_GEMM);
    cudaFuncSetAttribute(mma_gemm<2, false>, cudaFuncAttributeMaxDynamicSharedMemorySize, SMEM_GEMM);
    cudaFuncSetAttribute(mma_gemm<2, true>,  cudaFuncAttributeMaxDynamicSharedMemorySize, SMEM_GEMM);

    __half *xf, *w1, *w2, *s1, *s2, *he, *hs;
    cudaGetSymbolAddress((void**)&xf, g_xf);
    cudaGetSymbolAddress((void**)&w1, g_w1); cudaGetSymbolAddress((void**)&w2, g_w2);
    cudaGetSymbolAddress((void**)&s1, g_s1); cudaGetSymbolAddress((void**)&s2, g_s2);
    cudaGetSymbolAddress((void**)&he, g_he); cudaGetSymbolAddress((void**)&hs, g_hs);

    static cudaStream_t s_side = nullptr, s_aux = nullptr;
    static cudaEvent_t  ev_fork = nullptr, ev_c1 = nullptr, ev_c2 = nullptr,
                        ev_router = nullptr, ev_aux = nullptr, ev_side = nullptr;
    if (!s_side) {
        cudaStreamCreateWithFlags(&s_side, cudaStreamNonBlocking);
        cudaStreamCreateWithFlags(&s_aux,  cudaStreamNonBlocking);
        cudaEventCreateWithFlags(&ev_fork,   cudaEventDisableTiming);
        cudaEventCreateWithFlags(&ev_c1,     cudaEventDisableTiming);
        cudaEventCreateWithFlags(&ev_c2,     cudaEventDisableTiming);
        cudaEventCreateWithFlags(&ev_router, cudaEventDisableTiming);
        cudaEventCreateWithFlags(&ev_aux,    cudaEventDisableTiming);
        cudaEventCreateWithFlags(&ev_side,   cudaEventDisableTiming);
    }

    // fork
    cudaEventRecord(ev_fork, 0);
    cudaStreamWaitEvent(s_side, ev_fork, 0);
    cudaStreamWaitEvent(s_aux,  ev_fork, 0);

    // side: converts + memset (shared-chain and GEMM2 prerequisites)
    convert1_kernel<<<(N4_C1 + 255) / 256, 256, 0, s_side>>>(W1, sW1, w1, s1);
    cudaEventRecord(ev_c1, s_side);
    convert2_kernel<<<(N4_C2 + 255) / 256, 256, 0, s_side>>>(W2, sW2, w2, s2);
    cudaMemsetAsync(out, 0, (size_t)TOK * DDIM * sizeof(float), s_side);
    cudaEventRecord(ev_c2, s_side);

    // main: routing chain (router also produces xf)
    zero_kernel<<<1, 32>>>();
    router_kernel<<<TOK / (8 * RT_TPW), 256>>>(x, gW, gb, shw, gate, xf);
    cudaEventRecord(ev_router, 0);

    // aux stream: overlaps the GEMMs
    cudaStreamWaitEvent(s_aux, ev_router, 0);
    aux_kernel<<<1, 1024, 0, s_aux>>>(gate, auxp);
    cudaEventRecord(ev_aux, s_aux);

    // side: SHARED chain (s1/s2/memset in-stream; xf via ev_router)
    cudaStreamWaitEvent(s_side, ev_router, 0);
    mma_gemm<1, true><<<dim3(HDIM / 128, TOK / 128, 1), 256, SMEM_GEMM, s_side>>>(
        xf, s1, sb1, hs, nullptr, DDIM, HDIM);
    mma_gemm<2, true><<<dim3(DDIM / 128, TOK / 128, 1), 256, SMEM_GEMM, s_side>>>(
        hs, s2, sb2, nullptr, out, HDIM, DDIM);
    cudaEventRecord(ev_side, s_side);

    // main: EXPERT chain
    cudaStreamWaitEvent(0, ev_c1, 0);
    mma_gemm<1, false><<<dim3(HDIM / 128, TOK / 128, NEXP), 256, SMEM_GEMM>>>(
        xf, w1, b1, he, nullptr, DDIM, HDIM);
    cudaStreamWaitEvent(0, ev_c2, 0);
    mma_gemm<2, false><<<dim3(DDIM / 128, TOK / 128, NEXP), 256, SMEM_GEMM>>>(
        he, w2, b2, nullptr, out, HDIM, DDIM);

    // join
    cudaStreamWaitEvent(0, ev_side, 0);
    cudaStreamWaitEvent(0, ev_aux, 0);
}

// round 17
// speedup vs baseline: 1.0280x; 1.0280x over previous
#include <cuda_runtime.h>
#include <cuda_fp16.h>
#include <math.h>
#include <stdint.h>

#define TOK  8192
#define DDIM 512
#define HDIM 2048
#define NEXP 4

// ---------------- device scratch ----------------
__device__ int   g_cnt[NEXP];
__device__ int   g_bucket[NEXP * TOK];
__device__ float g_sw[TOK];

__device__ __half g_xf[(size_t)TOK * DDIM];
__device__ __half g_he[(size_t)TOK * HDIM];           // expert-path hidden
__device__ __half g_hs[(size_t)TOK * HDIM];           // shared-path hidden
__device__ __half g_w1[(size_t)NEXP * DDIM * HDIM];   // [E][D][H]
__device__ __half g_w2[(size_t)NEXP * HDIM * DDIM];   // [E][H][D]
__device__ __half g_s1[(size_t)DDIM * HDIM];          // [D][H]
__device__ __half g_s2[(size_t)HDIM * DDIM];          // [H][D]

// ---------------- helpers ----------------
__device__ __forceinline__ uint32_t smem_u32(const void* p) {
    uint32_t a;
    asm("{ .reg .u64 t; cvta.to.shared.u64 t, %1; cvt.u32.u64 %0, t; }" : "=r"(a) : "l"(p));
    return a;
}
__device__ __forceinline__ void cp16(uint32_t dst, const void* src, bool valid) {
    int sz = valid ? 16 : 0;
    asm volatile("cp.async.cg.shared.global [%0], [%1], 16, %2;\n" :: "r"(dst), "l"(src), "r"(sz));
}
#define CP_COMMIT() asm volatile("cp.async.commit_group;\n" ::: "memory")
#define CP_WAIT2()  asm volatile("cp.async.wait_group 2;\n" ::: "memory")

__device__ __forceinline__ void ldsm4(uint32_t& r0, uint32_t& r1, uint32_t& r2, uint32_t& r3,
                                      uint32_t a) {
    asm volatile("ldmatrix.sync.aligned.m8n8.x4.shared.b16 {%0,%1,%2,%3}, [%4];"
        : "=r"(r0), "=r"(r1), "=r"(r2), "=r"(r3) : "r"(a));
}
__device__ __forceinline__ void ldsm4t(uint32_t& r0, uint32_t& r1, uint32_t& r2, uint32_t& r3,
                                       uint32_t a) {
    asm volatile("ldmatrix.sync.aligned.m8n8.x4.trans.shared.b16 {%0,%1,%2,%3}, [%4];"
        : "=r"(r0), "=r"(r1), "=r"(r2), "=r"(r3) : "r"(a));
}
__device__ __forceinline__ void mma16816(float* c, const uint32_t* a, const uint32_t* b) {
    asm volatile("mma.sync.aligned.m16n8k16.row.col.f32.f16.f16.f32 "
        "{%0,%1,%2,%3}, {%4,%5,%6,%7}, {%8,%9}, {%0,%1,%2,%3};"
        : "+f"(c[0]), "+f"(c[1]), "+f"(c[2]), "+f"(c[3])
        : "r"(a[0]), "r"(a[1]), "r"(a[2]), "r"(a[3]), "r"(b[0]), "r"(b[1]));
}

// vectorized global reduction add of a float2 (8B-aligned dst), sm_90+
__device__ __forceinline__ void red_add_v2(float* dst, float a, float b) {
    asm volatile("red.global.add.v2.f32 [%0], {%1, %2};"
        :: "l"(dst), "f"(a), "f"(b) : "memory");
}

// fast gelu: x * sigmoid(1.5957692*(x + 0.044715 x^3))  (tanh-form rewrite)
__device__ __forceinline__ float fast_gelu(float x) {
    float u = x * fmaf(0.07135481627f, x * x, 1.5957691216f);
    return __fdividef(x, 1.f + __expf(-u));
}

// ---------------- zero counters ----------------
__global__ void zero_kernel() {
    if (threadIdx.x < NEXP) g_cnt[threadIdx.x] = 0;
}

// ---------------- router: smem gW + 2 tokens/warp, fused x->fp16 ----------------
#define RT_TPW 2
__global__ __launch_bounds__(256)
void router_kernel(const float* __restrict__ x,
                   const float* __restrict__ gW,
                   const float* __restrict__ gb,
                   const float* __restrict__ shw,
                   float* __restrict__ gate_out,
                   __half* __restrict__ xf) {
    __shared__ float sgWt[NEXP][DDIM];   // gW transposed: [expert][d]
    const int tid = threadIdx.x;

    // cooperative load + transpose of gW (8 KB)
    #pragma unroll
    for (int r = 0; r < 2; r++) {
        int d = tid + 256 * r;
        float4 w = *(const float4*)(gW + 4 * d);
        sgWt[0][d] = w.x; sgWt[1][d] = w.y; sgWt[2][d] = w.z; sgWt[3][d] = w.w;
    }
    __syncthreads();

    const int wid = tid >> 5, lane = tid & 31;
    const int tbase = (blockIdx.x * 8 + wid) * RT_TPW;

    const float4* xr[RT_TPW];
    __half2* xo[RT_TPW];
    #pragma unroll
    for (int k = 0; k < RT_TPW; k++) {
        xr[k] = (const float4*)(x + (size_t)(tbase + k) * DDIM);
        xo[k] = (__half2*)(xf + (size_t)(tbase + k) * DDIM);
    }

    float a[RT_TPW][4];
    #pragma unroll
    for (int k = 0; k < RT_TPW; k++)
        #pragma unroll
        for (int e = 0; e < 4; e++) a[k][e] = 0.f;

    #pragma unroll
    for (int it = 0; it < 4; it++) {
        int j4 = lane + 32 * it;           // float4 index within a row
        float4 w[4];
        #pragma unroll
        for (int e = 0; e < 4; e++)
            w[e] = *(const float4*)(&sgWt[e][4 * j4]);   // conflict-free LDS.128
        #pragma unroll
        for (int k = 0; k < RT_TPW; k++) {
            float4 v = xr[k][j4];
            #pragma unroll
            for (int e = 0; e < 4; e++)
                a[k][e] = fmaf(v.x, w[e].x, fmaf(v.y, w[e].y,
                           fmaf(v.z, w[e].z, fmaf(v.w, w[e].w, a[k][e]))));
            xo[k][2 * j4]     = __halves2half2(__float2half(v.x), __float2half(v.y));
            xo[k][2 * j4 + 1] = __halves2half2(__float2half(v.z), __float2half(v.w));
        }
    }

    // butterfly-reduce accumulators across the warp
    #pragma unroll
    for (int off = 16; off > 0; off >>= 1)
        #pragma unroll
        for (int k = 0; k < RT_TPW; k++)
            #pragma unroll
            for (int e = 0; e < 4; e++)
                a[k][e] += __shfl_xor_sync(0xffffffffu, a[k][e], off);

    if (lane < RT_TPW) {
        int t = tbase + lane;
        float l[4];
        #pragma unroll
        for (int e = 0; e < 4; e++) l[e] = a[lane][e] + gb[e];
        float m = fmaxf(fmaxf(l[0], l[1]), fmaxf(l[2], l[3]));
        float ex[4], s = 0.f;
        #pragma unroll
        for (int e = 0; e < 4; e++) { ex[e] = expf(l[e] - m); s += ex[e]; }
        float inv = 1.f / s;
        float best = -1.f; int bi = 0;
        #pragma unroll
        for (int e = 0; e < 4; e++) {
            float g = ex[e] * inv;
            gate_out[4 * t + e] = g;
            if (g > best) { best = g; bi = e; }
        }
        float sig = 1.f / (1.f + expf(-shw[0]));
        g_sw[t] = (1.f - best) * sig;
        int pos = atomicAdd(&g_cnt[bi], 1);
        g_bucket[bi * TOK + pos] = t;
    }
}

// ---------------- aux loss ----------------
__global__ void aux_kernel(const float* __restrict__ gate, float* __restrict__ auxp) {
    __shared__ float4 s[1024];
    int tid = threadIdx.x;
    float4 a = make_float4(0.f, 0.f, 0.f, 0.f);
    for (int t = tid; t < TOK; t += 1024) {
        a.x += gate[4 * t + 0]; a.y += gate[4 * t + 1];
        a.z += gate[4 * t + 2]; a.w += gate[4 * t + 3];
    }
    s[tid] = a;
    __syncthreads();
    for (int off = 512; off > 0; off >>= 1) {
        if (tid < off) {
            s[tid].x += s[tid + off].x; s[tid].y += s[tid + off].y;
            s[tid].z += s[tid + off].z; s[tid].w += s[tid + off].w;
        }
        __syncthreads();
    }
    if (tid == 0) {
        const float invT = 1.f / (float)TOK;
        float gm[4] = { s[0].x * invT, s[0].y * invT, s[0].z * invT, s[0].w * invT };
        float aux = 0.f;
        #pragma unroll
        for (int e = 0; e < NEXP; e++) aux += ((float)g_cnt[e] * invT) * gm[e];
        *auxp = aux * (float)NEXP * 0.01f;
    }
}

// ---------------- split fp32 -> fp16 converts ----------------
#define N4_W  (NEXP * DDIM * HDIM / 4)
#define N4_S  (DDIM * HDIM / 4)
#define N4_C1 (N4_W + N4_S)             // W1 + sW1
#define N4_C2 (N4_W + N4_S)             // W2 + sW2

__global__ void convert1_kernel(const float* __restrict__ W1,
                                const float* __restrict__ sW1,
                                __half* w1, __half* s1) {
    int i = blockIdx.x * blockDim.x + threadIdx.x;
    if (i >= N4_C1) return;
    const float* src; __half* dst; int j = i;
    if (j < N4_W) { src = W1; dst = w1; }
    else { j -= N4_W; src = sW1; dst = s1; }
    float4 v = ((const float4*)src)[j];
    ((__half2*)dst)[2 * j]     = __halves2half2(__float2half(v.x), __float2half(v.y));
    ((__half2*)dst)[2 * j + 1] = __halves2half2(__float2half(v.z), __float2half(v.w));
}

__global__ void convert2_kernel(const float* __restrict__ W2,
                                const float* __restrict__ sW2,
                                __half* w2, __half* s2) {
    int i = blockIdx.x * blockDim.x + threadIdx.x;
    if (i >= N4_C2) return;
    const float* src; __half* dst; int j = i;
    if (j < N4_W) { src = W2; dst = w2; }
    else { j -= N4_W; src = sW2; dst = s2; }
    float4 v = ((const float4*)src)[j];
    ((__half2*)dst)[2 * j]     = __halves2half2(__float2half(v.x), __float2half(v.y));
    ((__half2*)dst)[2 * j + 1] = __halves2half2(__float2half(v.z), __float2half(v.w));
}

// ---------------- fp16 mma.sync GEMM, CTA 128x128, warp tile 64x32, 4-stage ----------------
// Compile-time K, N (strength-reduced addressing, partially unrolled mainloop).
// STAGE 1: A=xf, B=W1/sW1 -> fast_gelu -> he/hs
// STAGE 2: A=he/hs, B=W2/sW2 -> red.v2 into zeroed out (shared scaled by g_sw)
#define A_TILE_B 10240               // 128 rows * 80B
#define B_TILE_B 8704                // 32 rows * 272B
#define B_OFF    A_TILE_B
#define STAGE_B  (A_TILE_B + B_TILE_B)   // 18944
#define NSTAGE   4
#define SMEM_GEMM (NSTAGE * STAGE_B)     // 75776

template<int STAGE, bool SP, int K, int N>
__global__ __launch_bounds__(256, 2)
void mma_gemm(const __half* __restrict__ A_g,
              const __half* __restrict__ B_g,
              const float* __restrict__ bias_g,
              __half* __restrict__ hdst_g,
              float* __restrict__ outp)
{
    extern __shared__ __align__(16) char smem[];
    const int z = blockIdx.z;
    int Mtot = TOK;
    const int* bucket = nullptr;
    const __half* Bg = SP ? B_g : B_g + (size_t)z * (size_t)K * N;
    const float* bias = SP ? bias_g : bias_g + (size_t)z * N;
    if (!SP) {
        Mtot = g_cnt[z];
        if ((int)(blockIdx.y * 128) >= Mtot) return;
        bucket = g_bucket + z * TOK;
    }
    const int tid = threadIdx.x;
    const int wid = tid >> 5, lane = tid & 31;
    const int mbase = blockIdx.y * 128, nbase = blockIdx.x * 128;
    const uint32_t sb = smem_u32(smem);

    // ---- A loader ----
    const int rA0 = tid >> 2, rA1 = 64 + (tid >> 2);
    const int ck  = tid & 3;
    int tok0, tok1; bool v0, v1;
    if (!SP) {
        v0 = (mbase + rA0) < Mtot; tok0 = v0 ? bucket[mbase + rA0] : 0;
        v1 = (mbase + rA1) < Mtot; tok1 = v1 ? bucket[mbase + rA1] : 0;
    } else {
        v0 = v1 = true; tok0 = mbase + rA0; tok1 = mbase + rA1;
    }
    const __half* aP0 = A_g + (size_t)tok0 * K + ck * 8;
    const __half* aP1 = A_g + (size_t)tok1 * K + ck * 8;
    const uint32_t oA0 = (uint32_t)rA0 * 80 + ck * 16;
    const uint32_t oA1 = (uint32_t)rA1 * 80 + ck * 16;

    // ---- B loader: incrementally advanced pointer (compile-time stride) ----
    const int rB = tid >> 3, cB = tid & 7;
    const __half* bp = Bg + (size_t)rB * N + nbase + cB * 8;
    const uint32_t oB = (uint32_t)rB * 272 + cB * 16;

    #define LOAD_STAGE(stg, koff, bk) do {                                   \
        uint32_t b_ = sb + (uint32_t)(stg) * STAGE_B;                        \
        cp16(b_ + oA0, aP0 + (koff), v0);                                    \
        cp16(b_ + oA1, aP1 + (koff), v1);                                    \
        cp16(b_ + B_OFF + oB,       (bk), true);                             \
        cp16(b_ + B_OFF + oB + 128, (bk) + 64, true);                        \
    } while (0)

    constexpr int KT = K / 32;
    const __half* bk3 = bp;                       // B ptr for the stage being loaded
    LOAD_STAGE(0, 0, bk3);  CP_COMMIT(); bk3 += 32 * N;
    LOAD_STAGE(1, 32, bk3); CP_COMMIT(); bk3 += 32 * N;
    LOAD_STAGE(2, 64, bk3); CP_COMMIT(); bk3 += 32 * N;

    // ---- compute mapping: warp tile 64 (M) x 32 (N) ----
    const int warpM = (wid & 1) * 64;
    const int warpN = (wid >> 1) * 32;
    float acc[4][4][4];
    #pragma unroll
    for (int mi = 0; mi < 4; mi++)
        #pragma unroll
        for (int ni = 0; ni < 4; ni++)
            #pragma unroll
            for (int q = 0; q < 4; q++) acc[mi][ni][q] = 0.f;

    const uint32_t aRowOff = (uint32_t)(warpM + (lane & 15)) * 80 + (lane >> 4) * 16;
    const uint32_t bOffBase = (uint32_t)((lane & 7) + ((lane >> 3) & 1) * 8) * 272
                              + (uint32_t)warpN * 2 + (uint32_t)(lane >> 4) * 16;

    int s_c = 0;
    #pragma unroll 2
    for (int kt = 0; kt < KT; kt++) {
        CP_WAIT2();
        __syncthreads();
        if (kt + 3 < KT) {
            int s_l = s_c + 3; if (s_l >= NSTAGE) s_l -= NSTAGE;
            LOAD_STAGE(s_l, (kt + 3) * 32, bk3);
            bk3 += 32 * N;
        }
        CP_COMMIT();

        uint32_t base = sb + (uint32_t)s_c * STAGE_B;
        #pragma unroll
        for (int ks = 0; ks < 2; ks++) {
            uint32_t bF[4][2];
            #pragma unroll
            for (int p = 0; p < 2; p++) {
                uint32_t r0, r1, r2, r3;
                ldsm4t(r0, r1, r2, r3,
                       base + B_OFF + bOffBase + (uint32_t)ks * (16 * 272) + (uint32_t)p * 32);
                bF[2 * p][0] = r0; bF[2 * p][1] = r1;
                bF[2 * p + 1][0] = r2; bF[2 * p + 1][1] = r3;
            }
            uint32_t aF[4][4];
            #pragma unroll
            for (int mi = 0; mi < 4; mi++) {
                uint32_t ad = base + aRowOff + (uint32_t)mi * (16 * 80) + ks * 32;
                ldsm4(aF[mi][0], aF[mi][1], aF[mi][2], aF[mi][3], ad);
            }
            #pragma unroll
            for (int mi = 0; mi < 4; mi++)
                #pragma unroll
                for (int ni = 0; ni < 4; ni++)
                    mma16816(acc[mi][ni], aF[mi], bF[ni]);
        }
        s_c = (s_c + 1 == NSTAGE) ? 0 : s_c + 1;
    }

    // ---- epilogue ----
    float bb[4][2];
    #pragma unroll
    for (int ni = 0; ni < 4; ni++) {
        int n = nbase + warpN + ni * 8 + (lane & 3) * 2;
        bb[ni][0] = bias[n]; bb[ni][1] = bias[n + 1];
    }

    #pragma unroll
    for (int mi = 0; mi < 4; mi++) {
        #pragma unroll
        for (int h = 0; h < 2; h++) {
            int pos = mbase + warpM + mi * 16 + (lane >> 2) + h * 8;
            int et; bool ev;
            if (!SP) { ev = pos < Mtot; et = ev ? bucket[pos] : 0; }
            else { ev = true; et = pos; }
            if (!ev) continue;
            float swv = (STAGE == 2 && SP) ? g_sw[et] : 1.f;
            #pragma unroll
            for (int ni = 0; ni < 4; ni++) {
                int n = nbase + warpN + ni * 8 + (lane & 3) * 2;
                float u0 = acc[mi][ni][2 * h]     + bb[ni][0];
                float u1 = acc[mi][ni][2 * h + 1] + bb[ni][1];
                if (STAGE == 1) {
                    u0 = fast_gelu(u0);
                    u1 = fast_gelu(u1);
                    *(__half2*)(hdst_g + (size_t)et * HDIM + n) =
                        __halves2half2(__float2half(u0), __float2half(u1));
                } else {
                    red_add_v2(outp + (size_t)et * DDIM + n, swv * u0, swv * u1);
                }
            }
        }
    }
    #undef LOAD_STAGE
}

// ---------------- launch ----------------
extern "C" void kernel_launch(void* const* d_in, const int* in_sizes, int n_in,
                              void* d_out, int out_size) {
    const float* x   = (const float*)d_in[0];
    const float* gW  = (const float*)d_in[1];
    const float* gb  = (const float*)d_in[2];
    const float* W1  = (const float*)d_in[3];
    const float* b1  = (const float*)d_in[4];
    const float* W2  = (const float*)d_in[5];
    const float* b2  = (const float*)d_in[6];
    const float* sW1 = (const float*)d_in[7];
    const float* sb1 = (const float*)d_in[8];
    const float* sW2 = (const float*)d_in[9];
    const float* sb2 = (const float*)d_in[10];
    const float* shw = (const float*)d_in[11];

    float* out  = (float*)d_out;
    float* auxp = out + (size_t)TOK * DDIM;
    float* gate = auxp + 1;

    cudaFuncSetAttribute(mma_gemm<1, false, DDIM, HDIM>, cudaFuncAttributeMaxDynamicSharedMemorySize, SMEM_GEMM);
    cudaFuncSetAttribute(mma_gemm<1, true,  DDIM, HDIM>, cudaFuncAttributeMaxDynamicSharedMemorySize, SMEM_GEMM);
    cudaFuncSetAttribute(mma_gemm<2, false, HDIM, DDIM>, cudaFuncAttributeMaxDynamicSharedMemorySize, SMEM_GEMM);
    cudaFuncSetAttribute(mma_gemm<2, true,  HDIM, DDIM>, cudaFuncAttributeMaxDynamicSharedMemorySize, SMEM_GEMM);

    __half *xf, *w1, *w2, *s1, *s2, *he, *hs;
    cudaGetSymbolAddress((void**)&xf, g_xf);
    cudaGetSymbolAddress((void**)&w1, g_w1); cudaGetSymbolAddress((void**)&w2, g_w2);
    cudaGetSymbolAddress((void**)&s1, g_s1); cudaGetSymbolAddress((void**)&s2, g_s2);
    cudaGetSymbolAddress((void**)&he, g_he); cudaGetSymbolAddress((void**)&hs, g_hs);

    static cudaStream_t s_side = nullptr, s_aux = nullptr;
    static cudaEvent_t  ev_fork = nullptr, ev_c1 = nullptr, ev_c2 = nullptr,
                        ev_router = nullptr, ev_aux = nullptr, ev_side = nullptr;
    if (!s_side) {
        cudaStreamCreateWithFlags(&s_side, cudaStreamNonBlocking);
        cudaStreamCreateWithFlags(&s_aux,  cudaStreamNonBlocking);
        cudaEventCreateWithFlags(&ev_fork,   cudaEventDisableTiming);
        cudaEventCreateWithFlags(&ev_c1,     cudaEventDisableTiming);
        cudaEventCreateWithFlags(&ev_c2,     cudaEventDisableTiming);
        cudaEventCreateWithFlags(&ev_router, cudaEventDisableTiming);
        cudaEventCreateWithFlags(&ev_aux,    cudaEventDisableTiming);
        cudaEventCreateWithFlags(&ev_side,   cudaEventDisableTiming);
    }

    // fork
    cudaEventRecord(ev_fork, 0);
    cudaStreamWaitEvent(s_side, ev_fork, 0);
    cudaStreamWaitEvent(s_aux,  ev_fork, 0);

    // side: converts + memset (shared-chain and GEMM2 prerequisites)
    convert1_kernel<<<(N4_C1 + 255) / 256, 256, 0, s_side>>>(W1, sW1, w1, s1);
    cudaEventRecord(ev_c1, s_side);
    convert2_kernel<<<(N4_C2 + 255) / 256, 256, 0, s_side>>>(W2, sW2, w2, s2);
    cudaMemsetAsync(out, 0, (size_t)TOK * DDIM * sizeof(float), s_side);
    cudaEventRecord(ev_c2, s_side);

    // main: routing chain (router also produces xf)
    zero_kernel<<<1, 32>>>();
    router_kernel<<<TOK / (8 * RT_TPW), 256>>>(x, gW, gb, shw, gate, xf);
    cudaEventRecord(ev_router, 0);

    // aux stream: overlaps the GEMMs
    cudaStreamWaitEvent(s_aux, ev_router, 0);
    aux_kernel<<<1, 1024, 0, s_aux>>>(gate, auxp);
    cudaEventRecord(ev_aux, s_aux);

    // side: SHARED chain (s1/s2/memset in-stream; xf via ev_router)
    cudaStreamWaitEvent(s_side, ev_router, 0);
    mma_gemm<1, true, DDIM, HDIM><<<dim3(HDIM / 128, TOK / 128, 1), 256, SMEM_GEMM, s_side>>>(
        xf, s1, sb1, hs, nullptr);
    mma_gemm<2, true, HDIM, DDIM><<<dim3(DDIM / 128, TOK / 128, 1), 256, SMEM_GEMM, s_side>>>(
        hs, s2, sb2, nullptr, out);
    cudaEventRecord(ev_side, s_side);

    // main: EXPERT chain
    cudaStreamWaitEvent(0, ev_c1, 0);
    mma_gemm<1, false, DDIM, HDIM><<<dim3(HDIM / 128, TOK / 128, NEXP), 256, SMEM_GEMM>>>(
        xf, w1, b1, he, nullptr);
    cudaStreamWaitEvent(0, ev_c2, 0);
    mma_gemm<2, false, HDIM, DDIM><<<dim3(DDIM / 128, TOK / 128, NEXP), 256, SMEM_GEMM>>>(
        he, w2, b2, nullptr, out);

    // join
    cudaStreamWaitEvent(0, ev_side, 0);
    cudaStreamWaitEvent(0, ev_aux, 0);
}